// round 16
// baseline (speedup 1.0000x reference)
#include <cuda_runtime.h>
#include <cuda_fp16.h>
#include <cstdint>

#define BATCH 512
#define IDIM 256
#define ODIM 256
#define CDIM 128
#define HDIM 128
#define IO (IDIM * ODIM)        // 65536
#define W2COLS (IO + ODIM)      // 65792
#define KTOT (HDIM * IDIM)      // 32768
#define KE 384                  // extended K: 256 (x/base) + 128 (h/biascols)
#define NSLICES 37              // 36 x (14 main BK64) + 1 x (8 main + 6 ext)
#define BM 256
#define BN 128
#define BK 64
#define NST 14                  // stages per slice (uniform)

// ------------------------- device scratch (no allocs) -----------------------
__device__ __half g_X[(size_t)BATCH * IDIM];                // 256 KB, [b][i]
__device__ __half g_H[(size_t)129 * BATCH];                 // [hh][b]; row 128 = 1.0
__device__ __half g_Zext[(size_t)BATCH * KE];
__device__ float g_part[(size_t)NSLICES * BATCH * ODIM];

// ------------------------- PTX helpers --------------------------------------
__device__ __forceinline__ uint32_t smem_u32(const void* p) {
    uint32_t a;
    asm("{ .reg .u64 t; cvta.to.shared.u64 t, %1; cvt.u32.u64 %0, t; }"
        : "=r"(a) : "l"(p));
    return a;
}
__device__ __forceinline__ void cp16(uint32_t s, const void* g) {
    asm volatile("cp.async.cg.shared.global [%0], [%1], 16;" :: "r"(s), "l"(g));
}
#define CP_COMMIT() asm volatile("cp.async.commit_group;" ::: "memory")
#define CP_WAIT(n)  asm volatile("cp.async.wait_group %0;" :: "n"(n) : "memory")

#define LDSM4(r0, r1, r2, r3, addr) \
    asm volatile("ldmatrix.sync.aligned.m8n8.x4.shared.b16 {%0,%1,%2,%3}, [%4];" \
        : "=r"(r0), "=r"(r1), "=r"(r2), "=r"(r3) : "r"(addr))

#define LDSM4T(r0, r1, r2, r3, addr) \
    asm volatile("ldmatrix.sync.aligned.m8n8.x4.trans.shared.b16 {%0,%1,%2,%3}, [%4];" \
        : "=r"(r0), "=r"(r1), "=r"(r2), "=r"(r3) : "r"(addr))

#define MMA16816(c, a, b0, b1) \
    asm volatile("mma.sync.aligned.m16n8k16.row.col.f32.f16.f16.f32 " \
        "{%0,%1,%2,%3}, {%4,%5,%6,%7}, {%8,%9}, {%0,%1,%2,%3};" \
        : "+f"((c)[0]), "+f"((c)[1]), "+f"((c)[2]), "+f"((c)[3]) \
        : "r"((a)[0]), "r"((a)[1]), "r"((a)[2]), "r"((a)[3]), "r"(b0), "r"(b1))

#define HMUL2(d, s) asm volatile("mul.f16x2 %0, %0, %1;" : "+r"(d) : "r"(s))

__device__ __forceinline__ uint32_t pack_h2(float lo, float hi) {
    __half2 h = __float22half2_rn(make_float2(lo, hi));
    return *(uint32_t*)&h;
}

// ------------------------- prep kernel (Z side only) -------------------------
// 128 blocks x 256 threads; each block stages w1 in smem once and handles
// 4 batch rows: h-GEMV from smem, g_X/g_H/g_Zext writes.
#define PREP_SMEM (CDIM * HDIM * 4 + 4 * CDIM * 4 + 4 * IDIM * 4)  // 71680

__global__ void __launch_bounds__(256)
prep_kernel(const float* __restrict__ x,
            const float* __restrict__ cond,
            const float* __restrict__ w1,
            const float* __restrict__ b1) {
    extern __shared__ float sm[];
    float* w1s = sm;                      // [128*128]
    float* cs  = sm + CDIM * HDIM;        // [4][128]
    float* xs  = cs + 4 * CDIM;           // [4][256]
    const int tid = threadIdx.x;
    const int b0 = blockIdx.x * 4;

    // stage cond/x for 4 rows (issue first — overlaps with w1 load)
#pragma unroll
    for (int r = 0; r < 2; r++) {
        int e = r * 256 + tid;            // 0..511 -> cs[4][128]
        cs[e] = cond[b0 * CDIM + e];
    }
#pragma unroll
    for (int r = 0; r < 4; r++) {
        int e = r * 256 + tid;            // 0..1023 -> xs[4][256]
        xs[e] = x[b0 * IDIM + e];
    }
    // stage w1 (64 KB) with high MLP
#pragma unroll
    for (int r = 0; r < 16; r++) {
        int e = r * 256 + tid;            // float4 index, 4096 total
        *(float4*)(w1s + e * 4) = *(const float4*)(w1 + e * 4);
    }
    __syncthreads();

#pragma unroll
    for (int bb = 0; bb < 4; bb++) {
        int b = b0 + bb;
        __half xh = __float2half_rn(xs[bb * IDIM + tid]);
        g_X[b * IDIM + tid] = xh;
        g_Zext[b * KE + tid] = xh;
        if (tid < HDIM) {
            int j = tid;
            float a0 = b1[j], a1 = 0.f, a2 = 0.f, a3 = 0.f;
            const float* cb = cs + bb * CDIM;
#pragma unroll 8
            for (int k = 0; k < CDIM; k += 4) {
                a0 = fmaf(cb[k],     w1s[(k)     * HDIM + j], a0);
                a1 = fmaf(cb[k + 1], w1s[(k + 1) * HDIM + j], a1);
                a2 = fmaf(cb[k + 2], w1s[(k + 2) * HDIM + j], a2);
                a3 = fmaf(cb[k + 3], w1s[(k + 3) * HDIM + j], a3);
            }
            __half hv = __float2half_rn(fmaxf((a0 + a1) + (a2 + a3), 0.0f));
            g_H[j * BATCH + b] = hv;
            g_Zext[b * KE + 256 + j] = hv;
        }
        if (tid == 255) g_H[128 * BATCH + b] = __float2half_rn(1.0f);
    }
}

// ------------------------- HMMA GEMM (A on-the-fly, B converted inline) -----
// C = (h∘x)@W (+ ext). A = x fp16 tile scaled by per-stage h in regs.
// B arrives fp32 via cp.async (3-deep ring) and is converted to the swizzled
// fp16 buffer at stage start (single 16K buffer, extra barrier).
// BM=256 x BN=128, 256 threads (8 warps, 4m x 2n, warp 64x64), BK=64.
// grid 2x2x37 = 148 CTAs. Prefetch distance 2, 3 buffers.
#define OFF_A(s)   ((uint32_t)(s) * 32768u)               // 3 x 32K
#define OFF_B32(s) (98304u + (uint32_t)(s) * 32768u)      // 3 x 32K fp32
#define OFF_HH(s)  (196608u + (uint32_t)(s) * 512u)       // 3 x 512
#define OFF_B16    198144u                                 // 16K fp16
#define SMEM_TOTAL (198144 + 16384)                        // 214528

__global__ void __launch_bounds__(256, 1)
gemm_hmma_kernel(const float* __restrict__ w2,
                 const float* __restrict__ baseW,
                 const float* __restrict__ b2) {
    extern __shared__ char smem[];
    const uint32_t sbase = smem_u32(smem);
    const int tid = threadIdx.x;
    const int wid = tid >> 5, lane = tid & 31;
    const int n0 = blockIdx.x * BN;
    const int m0 = blockIdx.y * BM;
    const int z = blockIdx.z;
    const bool mixed = (z == NSLICES - 1);

    const int m_base = (wid >> 1) * 64;   // 4 warps along M
    const int n_base = (wid & 1) * 64;    // 2 warps along N

    // stage kt: A (fp16, 2048 chunk16) + Bf32 (fp32, 2048 chunk16) + h column
    auto load_stage = [&](int kt) {
        int s = kt % 3;
        const __half* A;
        size_t kstrA;
        int kbA, hh;
        const float* Bsrc;      // fp32 row base (row stride varies)
        bool ext = mixed && kt >= 8;
        int kb = 0;
        if (!ext) {
            int k0 = (z * NST + kt) * BK;
            hh = k0 >> 8;
            A = g_X; kstrA = IDIM; kbA = k0 & 255;
            Bsrc = w2 + (size_t)hh * W2COLS + (size_t)(k0 & 255) * 256 + n0;
        } else {
            kb = (kt - 8) * BK;
            A = g_Zext; kstrA = KE; kbA = kb;
            hh = 128;
            Bsrc = nullptr;
        }
        // A: 256 rows x 128B -> 2048 chunks, 8 per thread
        uint32_t sa = sbase + OFF_A(s);
#pragma unroll
        for (int i = 0; i < 8; i++) {
            int t = tid + i * 256;
            int row = t >> 3, ch = t & 7;
            uint32_t sw = (uint32_t)row * 128 + ((ch ^ (row & 7)) << 4);
            cp16(sa + sw, A + (size_t)(m0 + row) * kstrA + kbA + ch * 8);
        }
        // Bf32: 64 rows x 512B linear -> 2048 chunk16, 8 per thread
        uint32_t sb32 = sbase + OFF_B32(s);
#pragma unroll
        for (int i = 0; i < 8; i++) {
            int c = tid + i * 256;
            int row = c >> 5, c16 = c & 31;
            const float* src;
            if (!ext) {
                src = Bsrc + (size_t)row * 256 + c16 * 4;
            } else {
                int k = kb + row;
                if (k < 256) src = baseW + (size_t)k * 256 + n0 + c16 * 4;
                else         src = w2 + (size_t)(k - 256) * W2COLS + IO + n0 + c16 * 4;
            }
            cp16(sb32 + (uint32_t)c * 16, src);
        }
        // h column: 256 rows x 2B = 512B
        if (tid < 32)
            cp16(sbase + OFF_HH(s) + tid * 16, g_H + hh * BATCH + m0 + tid * 8);
    };

    // convert Bf32[stage kt] -> Bf16 (swizzled), 8 chunk16 per thread
    auto convertB = [&](int kt) {
        int s = kt % 3;
        uint32_t sb32 = sbase + OFF_B32(s);
        uint32_t sb16 = sbase + OFF_B16;
        bool ext = mixed && kt >= 8;
        int kb = ext ? (kt - 8) * BK : 0;
#pragma unroll
        for (int i = 0; i < 8; i++) {
            int c = tid + i * 256;
            int row = c >> 5, c16 = c & 31;
            float4 v;
            asm volatile("ld.shared.v4.f32 {%0,%1,%2,%3}, [%4];"
                         : "=f"(v.x), "=f"(v.y), "=f"(v.z), "=f"(v.w)
                         : "r"(sb32 + (uint32_t)c * 16));
            if (ext) {
                int k = kb + row;
                if (k < 256) {
                    float4 c4 = *(const float4*)(b2 + (size_t)k * 256 + n0 + c16 * 4);
                    v.x += c4.x; v.y += c4.y; v.z += c4.z; v.w += c4.w;
                }
            }
            uint32_t u0 = pack_h2(v.x, v.y);
            uint32_t u1 = pack_h2(v.z, v.w);
            int ch = c16 >> 1, sub = c16 & 1;
            uint32_t dst = sb16 + (uint32_t)row * 256 +
                           (((uint32_t)ch ^ (row & 7)) << 4) + sub * 8;
            asm volatile("st.shared.v2.b32 [%0], {%1,%2};"
                         :: "r"(dst), "r"(u0), "r"(u1));
        }
    };

    float acc[4][8][4];
#pragma unroll
    for (int i = 0; i < 4; i++)
#pragma unroll
        for (int j = 0; j < 8; j++)
#pragma unroll
            for (int q = 0; q < 4; q++) acc[i][j][q] = 0.0f;

    const int arow_base = m_base + (lane & 15);
    const int asel = lane >> 4;
    const int brow_lane = lane & 15;
    const int bch_lane = (lane >> 4) & 1;
    const int hrow = m_base + (lane >> 2);

    load_stage(0); CP_COMMIT();
    load_stage(1); CP_COMMIT();

    for (int kt = 0; kt < NST; kt++) {
        CP_WAIT(1);            // stage kt arrived
        __syncthreads();       // prior Bf16 reads + buffer reuse safe
        if (kt + 2 < NST) load_stage(kt + 2);
        CP_COMMIT();

        convertB(kt);
        __syncthreads();       // Bf16 visible to all warps

        uint32_t sa = sbase + OFF_A(kt % 3);
        uint32_t sb16 = sbase + OFF_B16;

        uint32_t hq[4][2];
        uint32_t hbase = sbase + OFF_HH(kt % 3) + (uint32_t)hrow * 2;
#pragma unroll
        for (int mf = 0; mf < 4; mf++) {
            uint32_t t0, t1;
            asm volatile("ld.shared.u16 %0, [%1];" : "=r"(t0) : "r"(hbase + mf * 32));
            asm volatile("ld.shared.u16 %0, [%1];" : "=r"(t1) : "r"(hbase + mf * 32 + 16));
            hq[mf][0] = t0 | (t0 << 16);
            hq[mf][1] = t1 | (t1 << 16);
        }

#pragma unroll
        for (int kk = 0; kk < 4; kk++) {
            uint32_t a[4][4], bt[4][4];
#pragma unroll
            for (int mf = 0; mf < 4; mf++) {
                int row = arow_base + mf * 16;
                int ch = 2 * kk + asel;
                uint32_t ad = sa + row * 128 + ((ch ^ (row & 7)) << 4);
                LDSM4(a[mf][0], a[mf][1], a[mf][2], a[mf][3], ad);
                HMUL2(a[mf][0], hq[mf][0]);
                HMUL2(a[mf][2], hq[mf][0]);
                HMUL2(a[mf][1], hq[mf][1]);
                HMUL2(a[mf][3], hq[mf][1]);
            }
#pragma unroll
            for (int np = 0; np < 4; np++) {
                int row = kk * 16 + brow_lane;
                int ch = (n_base >> 3) + np * 2 + bch_lane;
                uint32_t bd = sb16 + row * 256 + ((ch ^ (row & 7)) << 4);
                LDSM4T(bt[np][0], bt[np][1], bt[np][2], bt[np][3], bd);
            }
#pragma unroll
            for (int mf = 0; mf < 4; mf++)
#pragma unroll
                for (int np = 0; np < 4; np++) {
                    MMA16816(acc[mf][2 * np], a[mf], bt[np][0], bt[np][1]);
                    MMA16816(acc[mf][2 * np + 1], a[mf], bt[np][2], bt[np][3]);
                }
        }
    }
    CP_WAIT(0);

    float* dst = g_part + (size_t)z * (BATCH * ODIM);
#pragma unroll
    for (int mf = 0; mf < 4; mf++) {
#pragma unroll
        for (int nf = 0; nf < 8; nf++) {
            int m = m0 + m_base + mf * 16 + (lane >> 2);
            int o = n0 + n_base + nf * 8 + (lane & 3) * 2;
            float2 v0 = make_float2(acc[mf][nf][0], acc[mf][nf][1]);
            float2 v1 = make_float2(acc[mf][nf][2], acc[mf][nf][3]);
            *(float2*)(dst + (size_t)m * ODIM + o) = v0;
            *(float2*)(dst + (size_t)(m + 8) * ODIM + o) = v1;
        }
    }
}

// ------------------------- split-K reduction + bias --------------------------
__global__ void reduce_kernel(const float* __restrict__ base_bias,
                              const float* __restrict__ b2,
                              float* __restrict__ out) {
    int b = blockIdx.x, o = threadIdx.x;
    float acc = base_bias[o] + b2[IO + o];
#pragma unroll
    for (int s = 0; s < NSLICES; s++)
        acc += g_part[((size_t)s * BATCH + b) * ODIM + o];
    out[b * ODIM + o] = acc;
}

// ------------------------- launcher -----------------------------------------
extern "C" void kernel_launch(void* const* d_in, const int* in_sizes, int n_in,
                              void* d_out, int out_size) {
    const float* x    = (const float*)d_in[0];
    const float* cond = (const float*)d_in[1];
    const float* bw   = (const float*)d_in[2];
    const float* bb   = (const float*)d_in[3];
    const float* w1   = (const float*)d_in[4];
    const float* b1   = (const float*)d_in[5];
    const float* w2   = (const float*)d_in[6];
    const float* b2   = (const float*)d_in[7];
    float* out = (float*)d_out;

    cudaFuncSetAttribute(prep_kernel,
                         cudaFuncAttributeMaxDynamicSharedMemorySize, PREP_SMEM);
    cudaFuncSetAttribute(gemm_hmma_kernel,
                         cudaFuncAttributeMaxDynamicSharedMemorySize, SMEM_TOTAL);

    prep_kernel<<<BATCH / 4, 256, PREP_SMEM>>>(x, cond, w1, b1);
    gemm_hmma_kernel<<<dim3(ODIM / BN, BATCH / BM, NSLICES), 256, SMEM_TOTAL>>>(
        w2, bw, b2);
    reduce_kernel<<<BATCH, 256>>>(bb, b2, out);
}

// round 17
// speedup vs baseline: 1.4723x; 1.4723x over previous
#include <cuda_runtime.h>
#include <cuda_fp16.h>
#include <cstdint>

#define BATCH 512
#define IDIM 256
#define ODIM 256
#define CDIM 128
#define HDIM 128
#define IO (IDIM * ODIM)        // 65536
#define W2COLS (IO + ODIM)      // 65792
#define KTOT (HDIM * IDIM)      // 32768
#define KE 384                  // extended K: 256 (x/base) + 128 (h/biascols)
#define NSLICES 37              // 36 x (14 main BK64) + 1 x (8 main + 6 ext)
#define BM 256
#define BN 128
#define BK 64
#define NST 14                  // stages per slice (uniform)

// ------------------------- device scratch (no allocs) -----------------------
__device__ float g_w1T[CDIM * HDIM];                        // [j][k], 64 KB
__device__ __half g_X[(size_t)BATCH * IDIM];                // 256 KB, [b][i]
__device__ __half g_H[(size_t)129 * BATCH];                 // [hh][b]; row 128 = 1.0
__device__ __half g_Zext[(size_t)BATCH * KE];
__device__ float g_part[(size_t)NSLICES * BATCH * ODIM];

// ------------------------- PTX helpers --------------------------------------
__device__ __forceinline__ uint32_t smem_u32(const void* p) {
    uint32_t a;
    asm("{ .reg .u64 t; cvta.to.shared.u64 t, %1; cvt.u32.u64 %0, t; }"
        : "=r"(a) : "l"(p));
    return a;
}
__device__ __forceinline__ void cp16(uint32_t s, const void* g) {
    asm volatile("cp.async.cg.shared.global [%0], [%1], 16;" :: "r"(s), "l"(g));
}
#define CP_COMMIT() asm volatile("cp.async.commit_group;" ::: "memory")
#define CP_WAIT(n)  asm volatile("cp.async.wait_group %0;" :: "n"(n) : "memory")

#define LDSM4(r0, r1, r2, r3, addr) \
    asm volatile("ldmatrix.sync.aligned.m8n8.x4.shared.b16 {%0,%1,%2,%3}, [%4];" \
        : "=r"(r0), "=r"(r1), "=r"(r2), "=r"(r3) : "r"(addr))

#define LDSM4T(r0, r1, r2, r3, addr) \
    asm volatile("ldmatrix.sync.aligned.m8n8.x4.trans.shared.b16 {%0,%1,%2,%3}, [%4];" \
        : "=r"(r0), "=r"(r1), "=r"(r2), "=r"(r3) : "r"(addr))

#define MMA16816(c, a, b0, b1) \
    asm volatile("mma.sync.aligned.m16n8k16.row.col.f32.f16.f16.f32 " \
        "{%0,%1,%2,%3}, {%4,%5,%6,%7}, {%8,%9}, {%0,%1,%2,%3};" \
        : "+f"((c)[0]), "+f"((c)[1]), "+f"((c)[2]), "+f"((c)[3]) \
        : "r"((a)[0]), "r"((a)[1]), "r"((a)[2]), "r"((a)[3]), "r"(b0), "r"(b1))

#define HMUL2(d, s) asm volatile("mul.f16x2 %0, %0, %1;" : "+r"(d) : "r"(s))

__device__ __forceinline__ uint32_t pack_h2(float lo, float hi) {
    __half2 h = __float22half2_rn(make_float2(lo, hi));
    return *(uint32_t*)&h;
}

// ------------------------- w1 transpose (tiny, one-time) ---------------------
// 16 blocks x 256 threads; 32x32 tiles.
__global__ void __launch_bounds__(256)
transpose_w1_kernel(const float* __restrict__ w1) {
    __shared__ float ts[32][33];
    int bx = blockIdx.x & 3, by = blockIdx.x >> 2;
    int c = threadIdx.x & 31, r = threadIdx.x >> 5;  // r: 0..7
#pragma unroll
    for (int i = 0; i < 4; i++) {
        int row = by * 32 + r + 8 * i;
        ts[r + 8 * i][c] = w1[row * HDIM + bx * 32 + c];
    }
    __syncthreads();
#pragma unroll
    for (int i = 0; i < 4; i++) {
        int j = bx * 32 + r + 8 * i;
        g_w1T[j * CDIM + by * 32 + c] = ts[c][r + 8 * i];
    }
}

// ------------------------- prep kernel (fast GEMV via w1T) -------------------
// 256 blocks x 256 threads; 2 batch rows each. Thread (rr, j) computes
// h[b0+rr][j] with float4 reads of w1T[j] (L2-resident) + smem-broadcast cond.
__global__ void __launch_bounds__(256)
prep_kernel(const float* __restrict__ x,
            const float* __restrict__ cond,
            const float* __restrict__ b1) {
    __shared__ float cs[2][CDIM];
    const int tid = threadIdx.x;
    const int b0 = blockIdx.x * 2;

    cs[tid >> 7][tid & 127] = cond[b0 * CDIM + tid];
    // x rows -> g_X / g_Zext (2 rows x 256)
#pragma unroll
    for (int rr = 0; rr < 2; rr++) {
        __half xh = __float2half_rn(x[(b0 + rr) * IDIM + tid]);
        g_X[(b0 + rr) * IDIM + tid] = xh;
        g_Zext[(b0 + rr) * KE + tid] = xh;
    }
    __syncthreads();

    const int j = tid & 127, rr = tid >> 7;
    const int b = b0 + rr;
    const float* wr = g_w1T + j * CDIM;
    const float* cb = cs[rr];
    float a0 = b1[j], a1 = 0.f, a2 = 0.f, a3 = 0.f;
#pragma unroll
    for (int k = 0; k < CDIM; k += 8) {
        float4 wa = *(const float4*)(wr + k);
        float4 wb = *(const float4*)(wr + k + 4);
        a0 = fmaf(cb[k],     wa.x, a0);
        a1 = fmaf(cb[k + 1], wa.y, a1);
        a2 = fmaf(cb[k + 2], wa.z, a2);
        a3 = fmaf(cb[k + 3], wa.w, a3);
        a0 = fmaf(cb[k + 4], wb.x, a0);
        a1 = fmaf(cb[k + 5], wb.y, a1);
        a2 = fmaf(cb[k + 6], wb.z, a2);
        a3 = fmaf(cb[k + 7], wb.w, a3);
    }
    __half hv = __float2half_rn(fmaxf((a0 + a1) + (a2 + a3), 0.0f));
    g_H[j * BATCH + b] = hv;
    g_Zext[b * KE + 256 + j] = hv;
    if (tid < 2) g_H[128 * BATCH + b0 + tid] = __float2half_rn(1.0f);
}

// ------------------------- HMMA GEMM (A on-the-fly, B converted inline) -----
// C = (h∘x)@W (+ ext). A-tile = x fp16 tile scaled by per-stage h in regs.
// B-tile read DIRECTLY from fp32 w2/baseW/b2 via LDG, cvt to fp16, STS into
// swizzled smem. BM=256 x BN=128, 256 threads (8 warps, 4m x 2n, warp 64x64),
// BK=64, 4-stage pipeline. grid 2x2x37 = 148 CTAs = one per SM.
#define STG_BYTES 49664          // A 32K + B 16K + h 512 + pad
#define OFF_A 0
#define OFF_B 32768
#define OFF_H 49152
#define SMEM_TOTAL (4 * STG_BYTES)   // 198656

__global__ void __launch_bounds__(256, 1)
gemm_hmma_kernel(const float* __restrict__ w2,
                 const float* __restrict__ baseW,
                 const float* __restrict__ b2) {
    extern __shared__ char smem[];
    const uint32_t sbase = smem_u32(smem);
    const int tid = threadIdx.x;
    const int wid = tid >> 5, lane = tid & 31;
    const int n0 = blockIdx.x * BN;
    const int m0 = blockIdx.y * BM;
    const int z = blockIdx.z;
    const bool mixed = (z == NSLICES - 1);

    const int m_base = (wid >> 1) * 64;   // 4 warps along M
    const int n_base = (wid & 1) * 64;    // 2 warps along N

    // B load geometry: row = (tid>>4) + 16*i (i<4), col chunk = tid&15 (8 fp32)
    const int brow0 = tid >> 4;
    const int bcol = tid & 15;

    auto ldgB = [&](int kt, float4 (&Bv)[4][2]) {
        if (!mixed || kt < 8) {
            int k0 = (z * NST + kt) * BK;
            int hh = k0 >> 8, i0 = k0 & 255;
            const float* src = w2 + (size_t)hh * W2COLS + (size_t)i0 * 256
                               + n0 + bcol * 8;
#pragma unroll
            for (int i = 0; i < 4; i++) {
                const float* p = src + (size_t)(brow0 + i * 16) * 256;
                Bv[i][0] = *(const float4*)p;
                Bv[i][1] = *(const float4*)(p + 4);
            }
        } else {
            int kb = (kt - 8) * BK;
#pragma unroll
            for (int i = 0; i < 4; i++) {
                int r = kb + brow0 + i * 16;
                if (r < 256) {
                    const float* pa = baseW + (size_t)r * 256 + n0 + bcol * 8;
                    const float* pc = b2 + (size_t)r * 256 + n0 + bcol * 8;
                    float4 a0 = *(const float4*)pa, a1 = *(const float4*)(pa + 4);
                    float4 c0 = *(const float4*)pc, c1 = *(const float4*)(pc + 4);
                    Bv[i][0] = make_float4(a0.x + c0.x, a0.y + c0.y,
                                           a0.z + c0.z, a0.w + c0.w);
                    Bv[i][1] = make_float4(a1.x + c1.x, a1.y + c1.y,
                                           a1.z + c1.z, a1.w + c1.w);
                } else {
                    const float* p = w2 + (size_t)(r - 256) * W2COLS + IO
                                     + n0 + bcol * 8;
                    Bv[i][0] = *(const float4*)p;
                    Bv[i][1] = *(const float4*)(p + 4);
                }
            }
        }
    };

    auto stsB = [&](int kt, const float4 (&Bv)[4][2]) {
        uint32_t sb = sbase + (uint32_t)(kt & 3) * STG_BYTES;
#pragma unroll
        for (int i = 0; i < 4; i++) {
            int row = brow0 + i * 16;
            uint32_t sw = sb + OFF_B + (uint32_t)row * 256
                          + (((uint32_t)bcol ^ (row & 7)) << 4);
            uint32_t u0 = pack_h2(Bv[i][0].x, Bv[i][0].y);
            uint32_t u1 = pack_h2(Bv[i][0].z, Bv[i][0].w);
            uint32_t u2 = pack_h2(Bv[i][1].x, Bv[i][1].y);
            uint32_t u3 = pack_h2(Bv[i][1].z, Bv[i][1].w);
            asm volatile("st.shared.v4.b32 [%0], {%1,%2,%3,%4};"
                         :: "r"(sw), "r"(u0), "r"(u1), "r"(u2), "r"(u3));
        }
    };

    auto loadA = [&](int kt) {
        uint32_t sb = sbase + (uint32_t)(kt & 3) * STG_BYTES;
        const __half* A;
        size_t kstrA;
        int kb, hh;
        if (!mixed || kt < 8) {
            int k0 = (z * NST + kt) * BK;
            hh = k0 >> 8;
            A = g_X; kstrA = IDIM; kb = k0 & 255;
        } else {
            A = g_Zext; kstrA = KE; kb = (kt - 8) * BK;
            hh = 128;
        }
#pragma unroll
        for (int i = 0; i < 8; i++) {
            int t = tid + i * 256;
            int row = t >> 3, ch = t & 7;
            uint32_t sw = (uint32_t)row * 128 + ((ch ^ (row & 7)) << 4);
            cp16(sb + OFF_A + sw, A + (size_t)(m0 + row) * kstrA + kb + ch * 8);
        }
        if (tid < 32)
            cp16(sb + OFF_H + tid * 16, g_H + hh * BATCH + m0 + tid * 8);
    };

    float acc[4][8][4];
#pragma unroll
    for (int i = 0; i < 4; i++)
#pragma unroll
        for (int j = 0; j < 8; j++)
#pragma unroll
            for (int q = 0; q < 4; q++) acc[i][j][q] = 0.0f;

    const int arow_base = m_base + (lane & 15);
    const int asel = lane >> 4;
    const int brow_lane = lane & 15;          // k-row within k16 step
    const int bch_lane = (lane >> 4) & 1;     // n8 group select
    const int hrow = m_base + (lane >> 2);    // fragment-owner row

    float4 Bv[4][2];
    ldgB(0, Bv);
    loadA(0); CP_COMMIT();
    stsB(0, Bv);
    ldgB(1, Bv);
    loadA(1); CP_COMMIT();
    loadA(2); CP_COMMIT();

    for (int kt = 0; kt < NST; kt++) {
        CP_WAIT(2);            // stage kt arrived
        __syncthreads();       // all warps done with this buffer's prior use
        if (kt + 1 < NST) stsB(kt + 1, Bv);
        if (kt + 2 < NST) ldgB(kt + 2, Bv);
        if (kt + 3 < NST) loadA(kt + 3);
        CP_COMMIT();

        uint32_t sb = sbase + (uint32_t)(kt & 3) * STG_BYTES;

        // per-stage h scalars (packed to half2) for the 4 m-fragments
        uint32_t hq[4][2];
        uint32_t hbase = sb + OFF_H + (uint32_t)hrow * 2;
#pragma unroll
        for (int mf = 0; mf < 4; mf++) {
            uint32_t t0, t1;
            asm volatile("ld.shared.u16 %0, [%1];" : "=r"(t0) : "r"(hbase + mf * 32));
            asm volatile("ld.shared.u16 %0, [%1];" : "=r"(t1) : "r"(hbase + mf * 32 + 16));
            hq[mf][0] = t0 | (t0 << 16);
            hq[mf][1] = t1 | (t1 << 16);
        }

#pragma unroll
        for (int kk = 0; kk < 4; kk++) {
            uint32_t a[4][4], bt[4][4];
#pragma unroll
            for (int mf = 0; mf < 4; mf++) {
                int row = arow_base + mf * 16;
                int ch = 2 * kk + asel;
                uint32_t ad = sb + OFF_A + row * 128 + ((ch ^ (row & 7)) << 4);
                LDSM4(a[mf][0], a[mf][1], a[mf][2], a[mf][3], ad);
                HMUL2(a[mf][0], hq[mf][0]);
                HMUL2(a[mf][2], hq[mf][0]);
                HMUL2(a[mf][1], hq[mf][1]);
                HMUL2(a[mf][3], hq[mf][1]);
            }
#pragma unroll
            for (int np = 0; np < 4; np++) {
                int row = kk * 16 + brow_lane;
                int ch = (n_base >> 3) + np * 2 + bch_lane;
                uint32_t bd = sb + OFF_B + row * 256 + ((ch ^ (row & 7)) << 4);
                LDSM4T(bt[np][0], bt[np][1], bt[np][2], bt[np][3], bd);
            }
#pragma unroll
            for (int mf = 0; mf < 4; mf++)
#pragma unroll
                for (int np = 0; np < 4; np++) {
                    MMA16816(acc[mf][2 * np], a[mf], bt[np][0], bt[np][1]);
                    MMA16816(acc[mf][2 * np + 1], a[mf], bt[np][2], bt[np][3]);
                }
        }
    }
    CP_WAIT(0);

    float* dst = g_part + (size_t)z * (BATCH * ODIM);
#pragma unroll
    for (int mf = 0; mf < 4; mf++) {
#pragma unroll
        for (int nf = 0; nf < 8; nf++) {
            int m = m0 + m_base + mf * 16 + (lane >> 2);
            int o = n0 + n_base + nf * 8 + (lane & 3) * 2;
            float2 v0 = make_float2(acc[mf][nf][0], acc[mf][nf][1]);
            float2 v1 = make_float2(acc[mf][nf][2], acc[mf][nf][3]);
            *(float2*)(dst + (size_t)m * ODIM + o) = v0;
            *(float2*)(dst + (size_t)(m + 8) * ODIM + o) = v1;
        }
    }
}

// ------------------------- split-K reduction + bias --------------------------
__global__ void reduce_kernel(const float* __restrict__ base_bias,
                              const float* __restrict__ b2,
                              float* __restrict__ out) {
    int b = blockIdx.x, o = threadIdx.x;
    float acc = base_bias[o] + b2[IO + o];
#pragma unroll
    for (int s = 0; s < NSLICES; s++)
        acc += g_part[((size_t)s * BATCH + b) * ODIM + o];
    out[b * ODIM + o] = acc;
}

// ------------------------- launcher -----------------------------------------
extern "C" void kernel_launch(void* const* d_in, const int* in_sizes, int n_in,
                              void* d_out, int out_size) {
    const float* x    = (const float*)d_in[0];
    const float* cond = (const float*)d_in[1];
    const float* bw   = (const float*)d_in[2];
    const float* bb   = (const float*)d_in[3];
    const float* w1   = (const float*)d_in[4];
    const float* b1   = (const float*)d_in[5];
    const float* w2   = (const float*)d_in[6];
    const float* b2   = (const float*)d_in[7];
    float* out = (float*)d_out;

    cudaFuncSetAttribute(gemm_hmma_kernel,
                         cudaFuncAttributeMaxDynamicSharedMemorySize, SMEM_TOTAL);

    transpose_w1_kernel<<<16, 256>>>(w1);
    prep_kernel<<<BATCH / 2, 256>>>(x, cond, b1);
    gemm_hmma_kernel<<<dim3(ODIM / BN, BATCH / BM, NSLICES), 256, SMEM_TOTAL>>>(
        w2, bw, b2);
    reduce_kernel<<<BATCH, 256>>>(bb, b2, out);
}